// round 16
// baseline (speedup 1.0000x reference)
#include <cuda_runtime.h>
#include <cstdint>

// Problem constants (fixed by the reference)
#define B   32
#define D   576
#define L   196
#define CC  10
#define K   256
#define M   (CC * K)          // 2560
#define NWP 8                 // packed words per (b,d) row
#define MAXSEL 64             // max selected literals per clause (mean ~11.5)

// Bit layout (fixed permutation, consistent between pack & clause kernels):
//   words 0..3 : element l = 4*j + k     (l < 128)  -> word k,   bit j (0..31)
//   words 4..7 : element l = 128+4*j+k   (128..195) -> word 4+k, bit j (0..16)

#define ROWS_PER_UNIT 2
// prep block roles (order: detect | ZERO | list | pack). Zero blocks first so
// their streaming stores start in wave 1, overlapping pack/list latency.
#define ZERO_BLOCKS   512
#define LIST_BLOCKS   (M / 8)                                  // 320
#define PACK_WARPS    ((B * D) / ROWS_PER_UNIT)                // 9216
#define PACK_BLOCKS   (PACK_WARPS / 8)                         // 1152
#define PREP_BLOCKS   (1 + ZERO_BLOCKS + LIST_BLOCKS + PACK_BLOCKS)  // 1985

#define Z4_TOTAL      ((B * M * L) / 4)                        // 4,014,080 uint4
#define ZERO_THREADS  (ZERO_BLOCKS * 256)                      // 131072

// ---------------- scratch (no allocation allowed) ----------------
// litbits word index = d*(B*NWP) + b*NWP + w  -> clause gathers hit ONE 128B line
__device__ uint32_t      g_litbits[D * B * NWP];  // 576 KB (L2-resident)
__device__ int16_t       g_idx[M * MAXSEL];       // per-clause selected d (padded)
__device__ int           g_cnt[M];                // per-clause count (0, or >=12, mult of 4)
__device__ int           g_mask_dtype;            // 0=uint8, 1=float32, 2=int32
__device__ volatile int  g_dt_ready;              // detect-done flag

// g_dt_ready across graph replays: detect rewrites g_mask_dtype (identical
// value, identical inputs) before setting the flag; a stale 1 from the prior
// replay lets list warps read either replay's dtype -- identical either way.

// ---------------- kernel 1: fused prep (detect | zero | list | pack) ----------------
__global__ void __launch_bounds__(256) prep_kernel(const float* __restrict__ lit,
                                                   const void*  __restrict__ mask,
                                                   float* __restrict__ out_map,
                                                   float* __restrict__ out_logits) {
    int lane = threadIdx.x & 31;
    int wblk = threadIdx.x >> 5;

    if (blockIdx.x == 0) {
        // ---- zero ALL B*CC logits (320 > blockDim: stride) + detect.
        for (int i = threadIdx.x; i < B * CC; i += blockDim.x)
            out_logits[i] = 0.0f;
        // Mask values are 0/1 booleans; as 32-bit words:
        //   float32 -> {0, 0x3F800000}; int32 -> {0,1}; uint8 -> packed bytes
        __shared__ int s_float, s_multi;
        if (threadIdx.x == 0) { s_float = 0; s_multi = 0; }
        __syncthreads();
        const uint32_t* w = (const uint32_t*)mask;
        for (int i = threadIdx.x; i < 4096; i += blockDim.x) {
            uint32_t v = w[i];
            if (v == 0x3F800000u) s_float = 1;            // benign race
            else if (v != 0u && v != 1u) s_multi = 1;
        }
        __syncthreads();
        if (threadIdx.x == 0) {
            g_mask_dtype = s_float ? 1 : (s_multi ? 0 : 2);
            __threadfence();
            g_dt_ready = 1;
        }
        return;
    }

    if (blockIdx.x <= ZERO_BLOCKS) {
        // ---- zero role: pure streaming STG.128 of out_map, grid-stride,
        // fully coalesced. Runs concurrently with latency-bound pack/list
        // warps on the same SMs (complementary pipe usage).
        int gt = (int)((blockIdx.x - 1) * 256 + threadIdx.x);   // 0..131071
        uint4* zp = (uint4*)out_map;
        uint4 z = make_uint4(0u, 0u, 0u, 0u);
        for (size_t i = gt; i < (size_t)Z4_TOTAL; i += ZERO_THREADS)
            zp[i] = z;
        return;
    }

    if (blockIdx.x <= ZERO_BLOCKS + LIST_BLOCKS) {
        // ---- list: warp per clause. Spin on dtype (block 0 is wave-1
        // resident -> no deadlock; value input-deterministic across replays),
        // then MLP-batched row load + ballot/popc compaction.
        int m = (int)(blockIdx.x - 1 - ZERO_BLOCKS) * 8 + wblk;
        while (g_dt_ready == 0) { __nanosleep(32); }
        __threadfence();
        int dt = g_mask_dtype;

        uint32_t vk[5][4];
        if (dt != 0) {
            // 4-byte elements: element d = c*128 + 4*lane + k
            const uint4* row4 = (const uint4*)((const uint32_t*)mask + (size_t)m * D);
            uint4 wv[5];
#pragma unroll
            for (int c = 0; c < 4; ++c) wv[c] = row4[c * 32 + lane];
            wv[4] = (lane < 16) ? row4[128 + lane] : make_uint4(0, 0, 0, 0);
#pragma unroll
            for (int c = 0; c < 5; ++c) {
                vk[c][0] = wv[c].x; vk[c][1] = wv[c].y;
                vk[c][2] = wv[c].z; vk[c][3] = wv[c].w;
            }
        } else {
            // 1-byte elements: word c*32+lane holds elements d = c*128+4*lane+k
            const uint32_t* row32 = (const uint32_t*)((const unsigned char*)mask + (size_t)m * D);
            uint32_t wv[5];
#pragma unroll
            for (int c = 0; c < 4; ++c) wv[c] = row32[c * 32 + lane];
            wv[4] = (lane < 16) ? row32[128 + lane] : 0u;
#pragma unroll
            for (int c = 0; c < 5; ++c) {
                vk[c][0] = wv[c] & 0xFFu;         vk[c][1] = (wv[c] >> 8) & 0xFFu;
                vk[c][2] = (wv[c] >> 16) & 0xFFu; vk[c][3] = (wv[c] >> 24) & 0xFFu;
            }
        }
        int cnt = 0, firstd = -1;
#pragma unroll
        for (int c = 0; c < 5; ++c)
#pragma unroll
            for (int k = 0; k < 4; ++k) {
                bool sel = (vk[c][k] != 0u);
                unsigned bal = __ballot_sync(0xFFFFFFFFu, sel);
                if (firstd < 0 && bal) firstd = c * 128 + 4 * (__ffs(bal) - 1) + k;
                int pos = cnt + __popc(bal & ((1u << lane) - 1u));
                if (sel && pos < MAXSEL)
                    g_idx[m * MAXSEL + pos] = (int16_t)(c * 128 + 4 * lane + k);
                cnt += __popc(bal);
            }
        if (cnt > MAXSEL) cnt = MAXSEL;
        // Padding (idempotent under AND): non-empty lists padded to >= 12
        // entries so the clause kernel can batch 12 loads unconditionally.
        int cnt4 = 0;
        if (cnt > 0) {
            cnt4 = (cnt + 3) & ~3;
            if (cnt4 < 12) cnt4 = 12;
            if (lane < cnt4 - cnt) g_idx[m * MAXSEL + cnt + lane] = (int16_t)firstd;
        }
        if (lane == 0) g_cnt[m] = cnt4;
        return;
    }

    // ---- pack: warp handles 2 consecutive (b,d) rows; 4 x LDG.128 upfront,
    // then register-only ballots. Store layout [d][b][8] words.
    int pw   = (int)(blockIdx.x - 1 - ZERO_BLOCKS - LIST_BLOCKS) * 8 + wblk;
    int row0 = pw * ROWS_PER_UNIT;                            // (b*D + d) index
    int b = row0 / D;
    int d = row0 - b * D;

    float4 ga[ROWS_PER_UNIT], gb[ROWS_PER_UNIT];
#pragma unroll
    for (int r = 0; r < ROWS_PER_UNIT; ++r) {
        const float4* rr = (const float4*)(lit + (size_t)(row0 + r) * L);
        ga[r] = rr[lane];                                     // l = 4*lane..+3
        gb[r] = (lane < 17) ? rr[32 + lane]                   // l = 128+4*lane..+3
                            : make_float4(0.f, 0.f, 0.f, 0.f);
    }

#pragma unroll
    for (int r = 0; r < ROWS_PER_UNIT; ++r) {
        unsigned w0 = __ballot_sync(0xFFFFFFFFu, ga[r].x > 0.5f);
        unsigned w1 = __ballot_sync(0xFFFFFFFFu, ga[r].y > 0.5f);
        unsigned w2 = __ballot_sync(0xFFFFFFFFu, ga[r].z > 0.5f);
        unsigned w3 = __ballot_sync(0xFFFFFFFFu, ga[r].w > 0.5f);
        unsigned w4 = __ballot_sync(0xFFFFFFFFu, gb[r].x > 0.5f);
        unsigned w5 = __ballot_sync(0xFFFFFFFFu, gb[r].y > 0.5f);
        unsigned w6 = __ballot_sync(0xFFFFFFFFu, gb[r].z > 0.5f);
        unsigned w7 = __ballot_sync(0xFFFFFFFFu, gb[r].w > 0.5f);

        unsigned out = w0;
        if (lane == 1) out = w1;
        if (lane == 2) out = w2;
        if (lane == 3) out = w3;
        if (lane == 4) out = w4;
        if (lane == 5) out = w5;
        if (lane == 6) out = w6;
        if (lane == 7) out = w7;
        if (lane < NWP) g_litbits[d * (B * NWP) + b * NWP + lane] = out;

        if (++d == D) { d = 0; ++b; }
    }
}

// ---------------- kernel 2: clause AND-reduce + SPARSE outputs ----------------
// One warp: clause m x 4 batches (grid (320,8)). Lanes = (bq 0..3) x (w 0..7);
// gather LDG (32 lanes, same d) hits ONE 128B line of g_litbits.
// out_map was pre-zeroed by prep (stream-ordered), so non-fired rows are
// SKIPPED entirely: ~80% of stores and unpack instructions vanish.
// Logits fused: fired clauses atomically add alpha*sign into out_logits.
__global__ void __launch_bounds__(256, 6)
clause_kernel(const float* __restrict__ alpha,
              float* __restrict__ out_map,
              float* __restrict__ out_or,
              float* __restrict__ out_logits) {
    int wblk = threadIdx.x >> 5;
    int lane = threadIdx.x & 31;
    int m  = blockIdx.x * 8 + wblk;                   // 320 x 8 = 2560
    int b0 = blockIdx.y * 4;                          // 8 x 4 = 32

    int bq = lane >> 3;                               // 0..3
    int w  = lane & 7;                                // 0..7

    int cnt4 = g_cnt[m];                              // 0, or >=12 mult of 4
    const int16_t* idxp = g_idx + m * MAXSEL;

    unsigned acc = 0xFFFFFFFFu;
    if (cnt4) {
        const uint32_t* base = g_litbits + (b0 + bq) * NWP + w;
        // 24B of indices (uint4 + uint2), then 12 independent litbits LDGs
        uint4 qa = ((const uint4*)idxp)[0];
        uint2 qb = ((const uint2*)idxp)[2];
        uint32_t qs[6] = { qa.x, qa.y, qa.z, qa.w, qb.x, qb.y };
        unsigned a[12];
#pragma unroll
        for (int k = 0; k < 6; ++k) {
            int dlo = (int)(qs[k] & 0xFFFFu);
            int dhi = (int)(qs[k] >> 16);
            a[2 * k]     = base[dlo * (B * NWP)];
            a[2 * k + 1] = base[dhi * (B * NWP)];
        }
#pragma unroll
        for (int k = 0; k < 12; ++k) acc &= a[k];
        // tail (cnt4 > 12 for ~38% of clauses)
        for (int i = 12; i < cnt4; i += 4) {
            uint64_t q = *(const uint64_t*)(idxp + i);
            acc &= base[(int)(q & 0xFFFFu) * (B * NWP)];
            acc &= base[(int)((q >> 16) & 0xFFFFu) * (B * NWP)];
            acc &= base[(int)((q >> 32) & 0xFFFFu) * (B * NWP)];
            acc &= base[(int)((q >> 48) & 0xFFFFu) * (B * NWP)];
        }
    }
    if (w >= 4) acc &= 0x1FFFFu;                      // group-B words: 17 valid bits

    // fire ballot: byte q of bal = fire bits for batch b0+q
    unsigned bal = __ballot_sync(0xFFFFFFFFu, acc != 0u);

    // ---- clause_map stores: ONLY fired rows (rest pre-zeroed by prep) ----
#pragma unroll
    for (int q = 0; q < 4; ++q) {
        unsigned anyq = (bal >> (q * 8)) & 0xFFu;     // warp-uniform
        if (anyq == 0) continue;                      // row stays zero
        uint4* row = (uint4*)(out_map + ((size_t)(b0 + q) * M + m) * L);
        unsigned w0 = __shfl_sync(0xFFFFFFFFu, acc, q * 8 + 0);
        unsigned w1 = __shfl_sync(0xFFFFFFFFu, acc, q * 8 + 1);
        unsigned w2 = __shfl_sync(0xFFFFFFFFu, acc, q * 8 + 2);
        unsigned w3 = __shfl_sync(0xFFFFFFFFu, acc, q * 8 + 3);
        uint4 v;
        v.x = ((w0 >> lane) & 1u) * 0x3F800000u;
        v.y = ((w1 >> lane) & 1u) * 0x3F800000u;
        v.z = ((w2 >> lane) & 1u) * 0x3F800000u;
        v.w = ((w3 >> lane) & 1u) * 0x3F800000u;
        row[lane] = v;
        unsigned w4 = __shfl_sync(0xFFFFFFFFu, acc, q * 8 + 4);
        unsigned w5 = __shfl_sync(0xFFFFFFFFu, acc, q * 8 + 5);
        unsigned w6 = __shfl_sync(0xFFFFFFFFu, acc, q * 8 + 6);
        unsigned w7 = __shfl_sync(0xFFFFFFFFu, acc, q * 8 + 7);
        if (lane < 17) {
            uint4 u;
            u.x = ((w4 >> lane) & 1u) * 0x3F800000u;
            u.y = ((w5 >> lane) & 1u) * 0x3F800000u;
            u.z = ((w6 >> lane) & 1u) * 0x3F800000u;
            u.w = ((w7 >> lane) & 1u) * 0x3F800000u;
            row[32 + lane] = u;
        }
    }

    // ---- clause_or + fused logits contribution ----
    if (lane < 4) {
        unsigned any = (bal >> (lane * 8)) & 0xFFu;
        int b = b0 + lane;
        out_or[b * M + m] = any ? 1.0f : 0.0f;
        if (any) {
            int c = m / K;
            int k = m - c * K;
            float sg  = (k < (K / 2)) ? 1.0f : -1.0f;
            atomicAdd(out_logits + b * CC + c, alpha[m] * sg);   // REDG
        }
    }
}

// ---------------- launch ----------------
extern "C" void kernel_launch(void* const* d_in, const int* in_sizes, int n_in,
                              void* d_out, int out_size) {
    const void* p_lit   = d_in[0];
    const void* p_mask  = d_in[1];
    const void* p_alpha = d_in[2];
    for (int i = 0; i < n_in; ++i) {
        if (in_sizes[i] == B * D * L)  p_lit   = d_in[i];
        else if (in_sizes[i] == M * D) p_mask  = d_in[i];
        else if (in_sizes[i] == M)     p_alpha = d_in[i];
    }
    const float* literals = (const float*)p_lit;
    const float* alpha    = (const float*)p_alpha;

    float* out_map    = (float*)d_out;                 // [B,M,L]
    float* out_or     = out_map + (size_t)B * M * L;   // [B,M]
    float* out_logits = out_or + (size_t)B * M;        // [B,CC]

    prep_kernel<<<PREP_BLOCKS, 256>>>(literals, p_mask, out_map, out_logits);

    dim3 cgrid(M / 8, B / 4);
    clause_kernel<<<cgrid, 256>>>(alpha, out_map, out_or, out_logits);
}

// round 17
// speedup vs baseline: 1.1780x; 1.1780x over previous
#include <cuda_runtime.h>
#include <cstdint>

// Problem constants (fixed by the reference)
#define B   32
#define D   576
#define L   196
#define CC  10
#define K   256
#define M   (CC * K)          // 2560
#define NWP 8                 // packed words per (b,d) row
#define MAXSEL 64             // max selected literals per clause (mean ~11.5)

// Bit layout (fixed permutation, consistent between pack & clause kernels):
//   words 0..3 : element l = 4*j + k     (l < 128)  -> word k,   bit j (0..31)
//   words 4..7 : element l = 128+4*j+k   (128..195) -> word 4+k, bit j (0..16)

#define ROWS_PER_UNIT 2
#define LIST_BLOCKS   (M / 8)                                  // 320
#define PACK_WARPS    ((B * D) / ROWS_PER_UNIT)                // 9216
#define PACK_BLOCKS   (PACK_WARPS / 8)                         // 1152
#define PREP_BLOCKS   (1 + LIST_BLOCKS + PACK_BLOCKS)          // 1473

// ---------------- scratch (no allocation allowed) ----------------
// litbits word index = d*(B*NWP) + b*NWP + w  -> clause gathers hit ONE 128B line
__device__ uint32_t      g_litbits[D * B * NWP];  // 576 KB (L2-resident)
__device__ int16_t       g_idx[M * MAXSEL];       // per-clause selected d (padded)
__device__ int           g_cnt[M];                // per-clause count (0, or >=12, mult of 4)
__device__ int           g_mask_dtype;            // 0=uint8, 1=float32, 2=int32
__device__ volatile int  g_dt_ready;              // detect-done flag

// g_dt_ready across graph replays: detect rewrites g_mask_dtype (identical
// value, identical inputs) before setting the flag; a stale 1 from the prior
// replay lets list warps read either replay's dtype -- identical either way.

// ---------------- kernel 1: fused prep (detect | list | pack) ----------------
__global__ void __launch_bounds__(256) prep_kernel(const float* __restrict__ lit,
                                                   const void*  __restrict__ mask,
                                                   float* __restrict__ out_logits) {
    int lane = threadIdx.x & 31;
    int wblk = threadIdx.x >> 5;

    if (blockIdx.x == 0) {
        // ---- zero ALL B*CC logits (320 > blockDim: stride) + detect.
        for (int i = threadIdx.x; i < B * CC; i += blockDim.x)
            out_logits[i] = 0.0f;
        // Mask values are 0/1 booleans; as 32-bit words:
        //   float32 -> {0, 0x3F800000}; int32 -> {0,1}; uint8 -> packed bytes
        // 1024 words suffice: ~20 expected ones at 2% density.
        __shared__ int s_float, s_multi;
        if (threadIdx.x == 0) { s_float = 0; s_multi = 0; }
        __syncthreads();
        const uint32_t* w = (const uint32_t*)mask;
        for (int i = threadIdx.x; i < 1024; i += blockDim.x) {
            uint32_t v = w[i];
            if (v == 0x3F800000u) s_float = 1;            // benign race
            else if (v != 0u && v != 1u) s_multi = 1;
        }
        __syncthreads();
        if (threadIdx.x == 0) {
            g_mask_dtype = s_float ? 1 : (s_multi ? 0 : 2);
            __threadfence();
            g_dt_ready = 1;
        }
        return;
    }

    if (blockIdx.x <= LIST_BLOCKS) {
        // ---- list: warp per clause. Spin on dtype (block 0 is wave-1
        // resident -> no deadlock; value input-deterministic across replays),
        // then MLP-batched row load + ballot/popc compaction.
        int m = (blockIdx.x - 1) * 8 + wblk;
        while (g_dt_ready == 0) { __nanosleep(32); }
        __threadfence();
        int dt = g_mask_dtype;

        uint32_t vk[5][4];
        if (dt != 0) {
            // 4-byte elements: element d = c*128 + 4*lane + k
            const uint4* row4 = (const uint4*)((const uint32_t*)mask + (size_t)m * D);
            uint4 wv[5];
#pragma unroll
            for (int c = 0; c < 4; ++c) wv[c] = row4[c * 32 + lane];
            wv[4] = (lane < 16) ? row4[128 + lane] : make_uint4(0, 0, 0, 0);
#pragma unroll
            for (int c = 0; c < 5; ++c) {
                vk[c][0] = wv[c].x; vk[c][1] = wv[c].y;
                vk[c][2] = wv[c].z; vk[c][3] = wv[c].w;
            }
        } else {
            // 1-byte elements: word c*32+lane holds elements d = c*128+4*lane+k
            const uint32_t* row32 = (const uint32_t*)((const unsigned char*)mask + (size_t)m * D);
            uint32_t wv[5];
#pragma unroll
            for (int c = 0; c < 4; ++c) wv[c] = row32[c * 32 + lane];
            wv[4] = (lane < 16) ? row32[128 + lane] : 0u;
#pragma unroll
            for (int c = 0; c < 5; ++c) {
                vk[c][0] = wv[c] & 0xFFu;         vk[c][1] = (wv[c] >> 8) & 0xFFu;
                vk[c][2] = (wv[c] >> 16) & 0xFFu; vk[c][3] = (wv[c] >> 24) & 0xFFu;
            }
        }
        int cnt = 0, firstd = -1;
#pragma unroll
        for (int c = 0; c < 5; ++c)
#pragma unroll
            for (int k = 0; k < 4; ++k) {
                bool sel = (vk[c][k] != 0u);
                unsigned bal = __ballot_sync(0xFFFFFFFFu, sel);
                if (firstd < 0 && bal) firstd = c * 128 + 4 * (__ffs(bal) - 1) + k;
                int pos = cnt + __popc(bal & ((1u << lane) - 1u));
                if (sel && pos < MAXSEL)
                    g_idx[m * MAXSEL + pos] = (int16_t)(c * 128 + 4 * lane + k);
                cnt += __popc(bal);
            }
        if (cnt > MAXSEL) cnt = MAXSEL;
        // Padding (idempotent under AND): non-empty lists padded to >= 12
        // entries so the clause kernel can batch 12 loads unconditionally.
        int cnt4 = 0;
        if (cnt > 0) {
            cnt4 = (cnt + 3) & ~3;
            if (cnt4 < 12) cnt4 = 12;
            if (lane < cnt4 - cnt) g_idx[m * MAXSEL + cnt + lane] = (int16_t)firstd;
        }
        if (lane == 0) g_cnt[m] = cnt4;
        return;
    }

    // ---- pack: warp handles 2 consecutive (b,d) rows; 4 x LDG.128 upfront,
    // then register-only ballots. Store layout [d][b][8] words.
    int pw   = (blockIdx.x - 1 - LIST_BLOCKS) * 8 + wblk;     // 0 .. PACK_WARPS-1
    int row0 = pw * ROWS_PER_UNIT;                            // (b*D + d) index
    int b = row0 / D;
    int d = row0 - b * D;

    float4 ga[ROWS_PER_UNIT], gb[ROWS_PER_UNIT];
#pragma unroll
    for (int r = 0; r < ROWS_PER_UNIT; ++r) {
        const float4* rr = (const float4*)(lit + (size_t)(row0 + r) * L);
        ga[r] = rr[lane];                                     // l = 4*lane..+3
        gb[r] = (lane < 17) ? rr[32 + lane]                   // l = 128+4*lane..+3
                            : make_float4(0.f, 0.f, 0.f, 0.f);
    }

#pragma unroll
    for (int r = 0; r < ROWS_PER_UNIT; ++r) {
        unsigned w0 = __ballot_sync(0xFFFFFFFFu, ga[r].x > 0.5f);
        unsigned w1 = __ballot_sync(0xFFFFFFFFu, ga[r].y > 0.5f);
        unsigned w2 = __ballot_sync(0xFFFFFFFFu, ga[r].z > 0.5f);
        unsigned w3 = __ballot_sync(0xFFFFFFFFu, ga[r].w > 0.5f);
        unsigned w4 = __ballot_sync(0xFFFFFFFFu, gb[r].x > 0.5f);
        unsigned w5 = __ballot_sync(0xFFFFFFFFu, gb[r].y > 0.5f);
        unsigned w6 = __ballot_sync(0xFFFFFFFFu, gb[r].z > 0.5f);
        unsigned w7 = __ballot_sync(0xFFFFFFFFu, gb[r].w > 0.5f);

        unsigned out = w0;
        if (lane == 1) out = w1;
        if (lane == 2) out = w2;
        if (lane == 3) out = w3;
        if (lane == 4) out = w4;
        if (lane == 5) out = w5;
        if (lane == 6) out = w6;
        if (lane == 7) out = w7;
        if (lane < NWP) g_litbits[d * (B * NWP) + b * NWP + lane] = out;

        if (++d == D) { d = 0; ++b; }
    }
}

// ---------------- kernel 2: clause AND-reduce + all outputs ----------------
// Grid (320, 4): 1280 blocks (~1.4 waves instead of 2.9). Each warp owns
// clause m and processes TWO b0-groups: idx regs reused, and unit 2's
// independent gather overlaps unit 1's store drain.
// Lanes = (bq 0..3) x (w 0..7); gather LDG (32 lanes, same d) hits ONE line.
// Dense stores (traffic-minimal: 64MB written exactly once). Zero rows use
// the shuffle-free fast path. Logits fused via atomicAdd (REDG).
__global__ void __launch_bounds__(256, 6)
clause_kernel(const float* __restrict__ alpha,
              float* __restrict__ out_map,
              float* __restrict__ out_or,
              float* __restrict__ out_logits) {
    int wblk = threadIdx.x >> 5;
    int lane = threadIdx.x & 31;
    int m = blockIdx.x * 8 + wblk;                    // 320 x 8 = 2560

    int bq = lane >> 3;                               // 0..3
    int w  = lane & 7;                                // 0..7

    int cnt4 = g_cnt[m];                              // 0, or >=12 mult of 4
    const int16_t* idxp = g_idx + m * MAXSEL;

    // index words loaded ONCE, reused for both b0 iterations
    uint32_t qs[6] = {0, 0, 0, 0, 0, 0};
    if (cnt4) {
        uint4 qa = ((const uint4*)idxp)[0];
        uint2 qb = ((const uint2*)idxp)[2];
        qs[0] = qa.x; qs[1] = qa.y; qs[2] = qa.z;
        qs[3] = qa.w; qs[4] = qb.x; qs[5] = qb.y;
    }

    // per-clause logits constants (uniform)
    int cc = m / K;
    int kk = m - cc * K;
    float sg = (kk < (K / 2)) ? 1.0f : -1.0f;
    float contrib = alpha[m] * sg;

#pragma unroll
    for (int it = 0; it < 2; ++it) {
        int b0 = blockIdx.y * 8 + it * 4;

        unsigned acc = 0xFFFFFFFFu;
        if (cnt4) {
            const uint32_t* base = g_litbits + (b0 + bq) * NWP + w;
            unsigned a[12];
#pragma unroll
            for (int k = 0; k < 6; ++k) {
                int dlo = (int)(qs[k] & 0xFFFFu);
                int dhi = (int)(qs[k] >> 16);
                a[2 * k]     = base[dlo * (B * NWP)];
                a[2 * k + 1] = base[dhi * (B * NWP)];
            }
#pragma unroll
            for (int k = 0; k < 12; ++k) acc &= a[k];
            // tail (cnt4 > 12 for ~38% of clauses); idx lines L1-hot
            for (int i = 12; i < cnt4; i += 4) {
                uint64_t q = *(const uint64_t*)(idxp + i);
                acc &= base[(int)(q & 0xFFFFu) * (B * NWP)];
                acc &= base[(int)((q >> 16) & 0xFFFFu) * (B * NWP)];
                acc &= base[(int)((q >> 32) & 0xFFFFu) * (B * NWP)];
                acc &= base[(int)((q >> 48) & 0xFFFFu) * (B * NWP)];
            }
        }
        if (w >= 4) acc &= 0x1FFFFu;                  // group-B words: 17 valid bits

        // fire ballot: byte q of bal = fire bits for batch b0+q
        unsigned bal = __ballot_sync(0xFFFFFFFFu, acc != 0u);

        // ---- clause_map stores: per batch row, 49 float4 slots ----
#pragma unroll
        for (int q = 0; q < 4; ++q) {
            uint4* row = (uint4*)(out_map + ((size_t)(b0 + q) * M + m) * L);
            unsigned anyq = (bal >> (q * 8)) & 0xFFu; // warp-uniform
            if (anyq == 0) {
                uint4 z = make_uint4(0u, 0u, 0u, 0u);
                row[lane] = z;
                if (lane < 17) row[32 + lane] = z;
                continue;
            }
            unsigned w0 = __shfl_sync(0xFFFFFFFFu, acc, q * 8 + 0);
            unsigned w1 = __shfl_sync(0xFFFFFFFFu, acc, q * 8 + 1);
            unsigned w2 = __shfl_sync(0xFFFFFFFFu, acc, q * 8 + 2);
            unsigned w3 = __shfl_sync(0xFFFFFFFFu, acc, q * 8 + 3);
            uint4 v;
            v.x = ((w0 >> lane) & 1u) * 0x3F800000u;
            v.y = ((w1 >> lane) & 1u) * 0x3F800000u;
            v.z = ((w2 >> lane) & 1u) * 0x3F800000u;
            v.w = ((w3 >> lane) & 1u) * 0x3F800000u;
            row[lane] = v;
            unsigned w4 = __shfl_sync(0xFFFFFFFFu, acc, q * 8 + 4);
            unsigned w5 = __shfl_sync(0xFFFFFFFFu, acc, q * 8 + 5);
            unsigned w6 = __shfl_sync(0xFFFFFFFFu, acc, q * 8 + 6);
            unsigned w7 = __shfl_sync(0xFFFFFFFFu, acc, q * 8 + 7);
            if (lane < 17) {
                uint4 u;
                u.x = ((w4 >> lane) & 1u) * 0x3F800000u;
                u.y = ((w5 >> lane) & 1u) * 0x3F800000u;
                u.z = ((w6 >> lane) & 1u) * 0x3F800000u;
                u.w = ((w7 >> lane) & 1u) * 0x3F800000u;
                row[32 + lane] = u;
            }
        }

        // ---- clause_or + fused logits contribution ----
        if (lane < 4) {
            unsigned any = (bal >> (lane * 8)) & 0xFFu;
            int b = b0 + lane;
            out_or[b * M + m] = any ? 1.0f : 0.0f;
            if (any)
                atomicAdd(out_logits + b * CC + cc, contrib);   // REDG
        }
    }
}

// ---------------- launch ----------------
extern "C" void kernel_launch(void* const* d_in, const int* in_sizes, int n_in,
                              void* d_out, int out_size) {
    const void* p_lit   = d_in[0];
    const void* p_mask  = d_in[1];
    const void* p_alpha = d_in[2];
    for (int i = 0; i < n_in; ++i) {
        if (in_sizes[i] == B * D * L)  p_lit   = d_in[i];
        else if (in_sizes[i] == M * D) p_mask  = d_in[i];
        else if (in_sizes[i] == M)     p_alpha = d_in[i];
    }
    const float* literals = (const float*)p_lit;
    const float* alpha    = (const float*)p_alpha;

    float* out_map    = (float*)d_out;                 // [B,M,L]
    float* out_or     = out_map + (size_t)B * M * L;   // [B,M]
    float* out_logits = out_or + (size_t)B * M;        // [B,CC]

    prep_kernel<<<PREP_BLOCKS, 256>>>(literals, p_mask, out_logits);

    dim3 cgrid(M / 8, B / 8);                          // (320, 4), 2 units/warp
    clause_kernel<<<cgrid, 256>>>(alpha, out_map, out_or, out_logits);
}